// round 13
// baseline (speedup 1.0000x reference)
#include <cuda_runtime.h>
#include <math_constants.h>
#include <cstdint>

#define NB 2
#define NPTS 8192
#define NQ (NB * NPTS)
#define SLICES 16
#define SLICE_CAND (NPTS / SLICES)     // 512
#define SLICE_PAIRS (SLICE_CAND / 2)   // 256
#define QPB 256                        // queries per k4 block
#define K4_THREADS 128
#define NENT (SLICES * 3)              // 48 partial entries per query
#define HENT (NENT / 2)                // 24 per merge-thread
#define TCH 16                         // tau sample chunks
#define CHCAND 256                     // candidates per chunk (sample = 4096)
#define CHPAIRS (CHCAND / 2)           // 128
#define NMINS (TCH * 4)                // 64 bucket mins per query
#define SAMPLE (TCH * CHCAND)          // 4096
#define REST (NPTS - SAMPLE)           // 4096 unsampled points per batch
#define INF CUDART_INF_F
#define SENTINEL 0x7fffffff
#define FULLM 0xffffffffu

// Candidate pair layout: pair j -> g_pairs[2j]=(x0,x1,y0,y1), g_pairs[2j+1]=(z0,z1,w0,w1)
__device__ float4 g_pairs[NB * (NPTS / 2) * 2];
__device__ float4 g_pts[NB * NPTS];                // (x,y,z,|p|^2) by original index
// Partials, transposed for coalescing: [slice*3+k][query]
__device__ float  g_pScore[NENT * NQ];
__device__ int    g_pIdx[NENT * NQ];
// Tau pipeline: bucket mins [chunk*4+bucket][query], then tau per query
__device__ float  g_tc[NMINS * NQ];
__device__ float  g_tau[NQ];

__device__ __forceinline__ uint64_t dup2(float v) {
    uint64_t r; asm("mov.b64 %0,{%1,%1};" : "=l"(r) : "f"(v)); return r;
}
__device__ __forceinline__ uint64_t fma2(uint64_t a, uint64_t b, uint64_t c) {
    uint64_t d; asm("fma.rn.f32x2 %0,%1,%2,%3;" : "=l"(d) : "l"(a), "l"(b), "l"(c)); return d;
}
__device__ __forceinline__ void unpack2(uint64_t v, float& lo, float& hi) {
    asm("mov.b64 {%0,%1},%2;" : "=f"(lo), "=f"(hi) : "l"(v));
}

// Branchy insert (fast when guarded by a rare outer test) — used in k4.
#define INS3(bs0, bs1, bs2, bi0, bi1, bi2, s, id)            \
    if ((s) < (bs2)) {                                       \
        if ((s) < (bs1)) {                                   \
            bs2 = bs1; bi2 = bi1;                            \
            if ((s) < (bs0)) { bs1 = bs0; bi1 = bi0;         \
                               bs0 = (s); bi0 = (id); }      \
            else             { bs1 = (s); bi1 = (id); }      \
        } else { bs2 = (s); bi2 = (id); }                    \
    }

// Branchless (select-based) insert — used in k5 so loads can be pipelined.
#define FINS3(s0, s1, s2, i0, i1, i2, s, id) do {            \
    bool p2 = (s) < (s2);                                    \
    bool p1 = (s) < (s1);                                    \
    bool p0 = (s) < (s0);                                    \
    s2 = p1 ? (s1) : (p2 ? (s) : (s2));                      \
    i2 = p1 ? (i1) : (p2 ? (id) : (i2));                     \
    s1 = p0 ? (s0) : (p1 ? (s) : (s1));                      \
    i1 = p0 ? (i0) : (p1 ? (id) : (i1));                     \
    s0 = p0 ? (s) : (s0);                                    \
    i0 = p0 ? (id) : (i0);                                   \
} while (0)

// Fused prep + tau bucket-min kernel. Sample = 4096 (chunks of 256 candidates).
#define K12_PREP_BLOCKS ((NB * REST) / 128)                    // = 64

__global__ void __launch_bounds__(128)
k12_prep_tau(const float* __restrict__ xyz1,
             const float* __restrict__ xyz2,
             const float* __restrict__ flow1) {
    const int tid = threadIdx.x;
    const int blk = blockIdx.x;

    if (blk >= 2048) {
        int e = (blk - 2048) * 128 + tid;          // 0 .. NB*REST-1
        int b = e >> 12;                           // REST = 4096
        int n = SAMPLE + (e & (REST - 1));         // SAMPLE .. NPTS-1
        const float* X = xyz1 + b * 3 * NPTS;
        const float* F = flow1 + b * 3 * NPTS;
        float px = X[n]            + F[n];
        float py = X[NPTS + n]     + F[NPTS + n];
        float pz = X[2 * NPTS + n] + F[2 * NPTS + n];
        float pw = fmaf(px, px, fmaf(py, py, pz * pz));
        g_pts[b * NPTS + n] = make_float4(px, py, pz, pw);
        float ox = __shfl_xor_sync(FULLM, px, 1);
        float oy = __shfl_xor_sync(FULLM, py, 1);
        float oz = __shfl_xor_sync(FULLM, pz, 1);
        float ow = __shfl_xor_sync(FULLM, pw, 1);
        if ((n & 1) == 0) {
            int j = b * (NPTS / 2) + (n >> 1);
            g_pairs[2 * j]     = make_float4(px, ox, py, oy);
            g_pairs[2 * j + 1] = make_float4(pz, oz, pw, ow);
        }
        return;
    }

    __shared__ float4 shp[CHPAIRS * 2];            // 4 KB chunk
    const int ch   = blk & (TCH - 1);
    const int qblk = blk >> 4;                     // 0..127; 64 qblks per batch
    const int b    = qblk >> 6;

    // Stage chunk ch of batch b: each thread computes 2 candidates.
#pragma unroll
    for (int half = 0; half < 2; half++) {
        const int lc = half * 128 + tid;           // 0..255 within chunk
        const int c  = ch * CHCAND + lc;
        const float* X = xyz1 + b * 3 * NPTS;
        const float* F = flow1 + b * 3 * NPTS;
        float px = X[c]            + F[c];
        float py = X[NPTS + c]     + F[NPTS + c];
        float pz = X[2 * NPTS + c] + F[2 * NPTS + c];
        float pw = fmaf(px, px, fmaf(py, py, pz * pz));
        float ox = __shfl_xor_sync(FULLM, px, 1);
        float oy = __shfl_xor_sync(FULLM, py, 1);
        float oz = __shfl_xor_sync(FULLM, pz, 1);
        float ow = __shfl_xor_sync(FULLM, pw, 1);
        if ((lc & 1) == 0) {
            int jj = lc >> 1;
            shp[2 * jj]     = make_float4(px, ox, py, oy);
            shp[2 * jj + 1] = make_float4(pz, oz, pw, ow);
        }
        if ((qblk & 63) == 0) {                    // writer block for (b, ch)
            g_pts[b * NPTS + c] = make_float4(px, py, pz, pw);
            if ((lc & 1) == 0) {
                int j = b * (NPTS / 2) + (c >> 1);
                g_pairs[2 * j]     = make_float4(px, ox, py, oy);
                g_pairs[2 * j + 1] = make_float4(pz, oz, pw, ow);
            }
        }
    }
    __syncthreads();

    const int q = qblk * 128 + tid;
    const int n = q & (NPTS - 1);
    const float* X2 = xyz2 + b * 3 * NPTS;
    const float qx = X2[n], qy = X2[NPTS + n], qz = X2[2 * NPTS + n];
    const uint64_t mx = dup2(-2.f * qx), my = dup2(-2.f * qy), mz = dup2(-2.f * qz);

    const ulonglong2* src = reinterpret_cast<const ulonglong2*>(shp);
    float m0 = INF, m1 = INF, m2 = INF, m3 = INF;
#pragma unroll 4
    for (int j = 0; j < CHPAIRS; j += 2) {
        ulonglong2 u0 = src[2 * j];
        ulonglong2 u1 = src[2 * j + 1];
        ulonglong2 v0 = src[2 * j + 2];
        ulonglong2 v1 = src[2 * j + 3];
        float a0, a1, c0, c1;
        unpack2(fma2(u0.x, mx, fma2(u0.y, my, fma2(u1.x, mz, u1.y))), a0, a1);
        unpack2(fma2(v0.x, mx, fma2(v0.y, my, fma2(v1.x, mz, v1.y))), c0, c1);
        m0 = fminf(m0, a0);
        m1 = fminf(m1, a1);
        m2 = fminf(m2, c0);
        m3 = fminf(m3, c1);
    }
    g_tc[(ch * 4 + 0) * NQ + q] = m0;
    g_tc[(ch * 4 + 1) * NQ + q] = m1;
    g_tc[(ch * 4 + 2) * NQ + q] = m2;
    g_tc[(ch * 4 + 3) * NQ + q] = m3;
}

// 3rd smallest of the 64 bucket mins (64 distinct candidates => >= global 3rd best).
__global__ void k3_tau2() {
    int q = blockIdx.x * blockDim.x + threadIdx.x;
    if (q >= NQ) return;
    float b0 = INF, b1 = INF, b2 = INF;
#pragma unroll 8
    for (int c = 0; c < NMINS; c++) {
        float s = g_tc[c * NQ + q];
        float t = fmaxf(b0, s);  b0 = fminf(b0, s);
        float u = fmaxf(b1, t);  b1 = fminf(b1, t);
        b2 = fminf(b2, u);
    }
    g_tau[q] = nextafterf(b2, CUDART_INF_F);
}

// 256 queries/block vs one 512-candidate slice (frozen config — measured 33.4us).
__global__ void __launch_bounds__(K4_THREADS)
k4_scan(const float* __restrict__ xyz2) {
    __shared__ float4 sh[SLICE_PAIRS * 2];   // 8 KB

    const int blk   = blockIdx.x;
    const int slice = blk & (SLICES - 1);
    const int qg    = blk >> 4;              // 0..63
    const int batch = qg >> 5;               // 32 qgroups per batch
    const int qbase = (qg & 31) * QPB;
    const int lane  = threadIdx.x & 31;
    const int w     = threadIdx.x >> 5;

    const float4* src = g_pairs + (size_t)(batch * (NPTS / 2) + slice * SLICE_PAIRS) * 2;
#pragma unroll
    for (int i = threadIdx.x; i < SLICE_PAIRS * 2; i += K4_THREADS)
        sh[i] = src[i];
    __syncthreads();

    const int qA = qbase + w * 64 + lane;
    const int qB = qA + 32;
    const int gqA = batch * NPTS + qA;
    const int gqB = batch * NPTS + qB;
    const float* X2 = xyz2 + batch * 3 * NPTS;
    const float aX = X2[qA], aY = X2[NPTS + qA], aZ = X2[2 * NPTS + qA];
    const float bX = X2[qB], bY = X2[NPTS + qB], bZ = X2[2 * NPTS + qB];

    const uint64_t Amx = dup2(-2.f * aX), Amy = dup2(-2.f * aY), Amz = dup2(-2.f * aZ);
    const uint64_t Bmx = dup2(-2.f * bX), Bmy = dup2(-2.f * bY), Bmz = dup2(-2.f * bZ);

    const float tA = g_tau[gqA];
    const float tB = g_tau[gqB];
    float As0 = tA, As1 = tA, As2 = tA;  int Ai0 = SENTINEL, Ai1 = SENTINEL, Ai2 = SENTINEL;
    float Bs0 = tB, Bs1 = tB, Bs2 = tB;  int Bi0 = SENTINEL, Bi1 = SENTINEL, Bi2 = SENTINEL;

    const uint32_t shbase = (uint32_t)__cvta_generic_to_shared(sh);
    const int cbase = slice * SLICE_CAND;

#pragma unroll 4
    for (int j = 0; j < SLICE_PAIRS; j += 2) {
        uint64_t xp0, yp0, zp0, wp0, xp1, yp1, zp1, wp1;
        const uint32_t addr = shbase + j * 32;
        asm("ld.shared.v2.u64 {%0,%1},[%2];"    : "=l"(xp0), "=l"(yp0) : "r"(addr));
        asm("ld.shared.v2.u64 {%0,%1},[%2+16];" : "=l"(zp0), "=l"(wp0) : "r"(addr));
        asm("ld.shared.v2.u64 {%0,%1},[%2+32];" : "=l"(xp1), "=l"(yp1) : "r"(addr));
        asm("ld.shared.v2.u64 {%0,%1},[%2+48];" : "=l"(zp1), "=l"(wp1) : "r"(addr));

        float a0, a1, a2, a3, b0, b1, b2, b3;
        unpack2(fma2(xp0, Amx, fma2(yp0, Amy, fma2(zp0, Amz, wp0))), a0, a1);
        unpack2(fma2(xp1, Amx, fma2(yp1, Amy, fma2(zp1, Amz, wp1))), a2, a3);
        unpack2(fma2(xp0, Bmx, fma2(yp0, Bmy, fma2(zp0, Bmz, wp0))), b0, b1);
        unpack2(fma2(xp1, Bmx, fma2(yp1, Bmy, fma2(zp1, Bmz, wp1))), b2, b3);

        if (fminf(fminf(a0, a1), fminf(a2, a3)) < As2) {
            const int id = cbase + 2 * j;
            INS3(As0, As1, As2, Ai0, Ai1, Ai2, a0, id);
            INS3(As0, As1, As2, Ai0, Ai1, Ai2, a1, id + 1);
            INS3(As0, As1, As2, Ai0, Ai1, Ai2, a2, id + 2);
            INS3(As0, As1, As2, Ai0, Ai1, Ai2, a3, id + 3);
        }
        if (fminf(fminf(b0, b1), fminf(b2, b3)) < Bs2) {
            const int id = cbase + 2 * j;
            INS3(Bs0, Bs1, Bs2, Bi0, Bi1, Bi2, b0, id);
            INS3(Bs0, Bs1, Bs2, Bi0, Bi1, Bi2, b1, id + 1);
            INS3(Bs0, Bs1, Bs2, Bi0, Bi1, Bi2, b2, id + 2);
            INS3(Bs0, Bs1, Bs2, Bi0, Bi1, Bi2, b3, id + 3);
        }
    }

    const int sb = slice * 3 * NQ;
    g_pScore[sb + 0 * NQ + gqA] = As0;  g_pIdx[sb + 0 * NQ + gqA] = Ai0;
    g_pScore[sb + 1 * NQ + gqA] = As1;  g_pIdx[sb + 1 * NQ + gqA] = Ai1;
    g_pScore[sb + 2 * NQ + gqA] = As2;  g_pIdx[sb + 2 * NQ + gqA] = Ai2;
    g_pScore[sb + 0 * NQ + gqB] = Bs0;  g_pIdx[sb + 0 * NQ + gqB] = Bi0;
    g_pScore[sb + 1 * NQ + gqB] = Bs1;  g_pIdx[sb + 1 * NQ + gqB] = Bi1;
    g_pScore[sb + 2 * NQ + gqB] = Bs2;  g_pIdx[sb + 2 * NQ + gqB] = Bi2;
}

// Two threads per query: each merges 24 entries branchless, triples exchanged
// via shfl and merged lower-slices-first (strict < keeps low-index tie-break
// because slices are ascending index ranges). h==0 runs the epilogue.
__global__ void __launch_bounds__(256)
k5_final(const float* __restrict__ xyz2,
         const float* __restrict__ flow1,
         float* __restrict__ out) {
    const int i = blockIdx.x * 256 + threadIdx.x;   // 0 .. 2*NQ-1
    const int q = i >> 1;
    const int h = i & 1;
    const int b = q >> 13, n = q & (NPTS - 1);

    float bs0 = INF, bs1 = INF, bs2 = INF;
    int   bi0 = 0,   bi1 = 0,   bi2 = 0;
    const int ebase = h * HENT;
#pragma unroll
    for (int e = 0; e < HENT; e++) {
        float s  = g_pScore[(ebase + e) * NQ + q];
        int   iv = g_pIdx[(ebase + e) * NQ + q];
        FINS3(bs0, bs1, bs2, bi0, bi1, bi2, s, iv);
    }

    // Exchange triples with partner (i ^ 1) and merge lower-half-first.
    float rs0 = __shfl_xor_sync(FULLM, bs0, 1);
    int   ri0 = __shfl_xor_sync(FULLM, bi0, 1);
    float rs1 = __shfl_xor_sync(FULLM, bs1, 1);
    int   ri1 = __shfl_xor_sync(FULLM, bi1, 1);
    float rs2 = __shfl_xor_sync(FULLM, bs2, 1);
    int   ri2 = __shfl_xor_sync(FULLM, bi2, 1);

    float m0, m1, m2, u0, u1, u2;
    int   j0, j1, j2, v0, v1, v2;
    if (h == 0) { m0 = bs0; m1 = bs1; m2 = bs2; j0 = bi0; j1 = bi1; j2 = bi2;
                  u0 = rs0; u1 = rs1; u2 = rs2; v0 = ri0; v1 = ri1; v2 = ri2; }
    else        { m0 = rs0; m1 = rs1; m2 = rs2; j0 = ri0; j1 = ri1; j2 = ri2;
                  u0 = bs0; u1 = bs1; u2 = bs2; v0 = bi0; v1 = bi1; v2 = bi2; }
    FINS3(m0, m1, m2, j0, j1, j2, u0, v0);
    FINS3(m0, m1, m2, j0, j1, j2, u1, v1);
    FINS3(m0, m1, m2, j0, j1, j2, u2, v2);

    if (h == 0) {
        const float* X2 = xyz2 + b * 3 * NPTS;
        const float qx = X2[n], qy = X2[NPTS + n], qz = X2[2 * NPTS + n];

        const float4* pts = g_pts + b * NPTS;
        int   pp[3] = { j0, j1, j2 };
        float wk[3];
        float wsum = 0.f;
#pragma unroll
        for (int k = 0; k < 3; k++) {
            float4 p = pts[pp[k]];
            float dx = p.x - qx, dy = p.y - qy, dz = p.z - qz;
            float d = sqrtf(fmaf(dx, dx, fmaf(dy, dy, dz * dz)));
            d = fmaxf(d, 1e-10f);
            float inv = 1.0f / d;
            wk[k] = inv;
            wsum += inv;
        }
        const float rs = 1.0f / wsum;

        const float* F = flow1 + b * 3 * NPTS;
        float fx = 0.f, fy = 0.f, fz = 0.f;
#pragma unroll
        for (int k = 0; k < 3; k++) {
            int o = pp[k];
            float ww = wk[k] * rs;
            fx = fmaf(ww, F[o],            fx);
            fy = fmaf(ww, F[NPTS + o],     fy);
            fz = fmaf(ww, F[2 * NPTS + o], fz);
        }

        float* O = out + b * 3 * NPTS;
        O[n]            = qx - fx;
        O[NPTS + n]     = qy - fy;
        O[2 * NPTS + n] = qz - fz;
    }
}

extern "C" void kernel_launch(void* const* d_in, const int* in_sizes, int n_in,
                              void* d_out, int out_size) {
    const float* xyz1  = (const float*)d_in[0];
    const float* xyz2  = (const float*)d_in[1];
    const float* flow1 = (const float*)d_in[2];
    float* out = (float*)d_out;

    k12_prep_tau<<<2048 + K12_PREP_BLOCKS, 128>>>(xyz1, xyz2, flow1);  // 2112 blocks
    k3_tau2<<<(NQ + 255) / 256, 256>>>();
    k4_scan<<<(NQ / QPB) * SLICES, K4_THREADS>>>(xyz2);                // 1024 blocks
    k5_final<<<(2 * NQ) / 256, 256>>>(xyz2, flow1, out);               // 128 blocks
}

// round 14
// speedup vs baseline: 1.0774x; 1.0774x over previous
#include <cuda_runtime.h>
#include <math_constants.h>
#include <cstdint>

#define NB 2
#define NPTS 8192
#define NQ (NB * NPTS)
#define SLICES 32
#define SLICE_CAND (NPTS / SLICES)     // 256
#define SLICE_PAIRS (SLICE_CAND / 2)   // 128
#define QPB 256                        // queries per k4 block
#define K4_THREADS 128
#define NENT (SLICES * 3)              // 96 partial entries per query
#define QT 4                           // k5 threads per query
#define HENT (NENT / QT)               // 24 per merge-thread
#define TCH 16                         // tau sample chunks
#define CHCAND 128                     // candidates per chunk (sample = 2048)
#define CHPAIRS (CHCAND / 2)           // 64
#define NMINS (TCH * 4)                // 64 bucket mins per query
#define SAMPLE (TCH * CHCAND)          // 2048
#define REST (NPTS - SAMPLE)           // 6144 unsampled points per batch
#define INF CUDART_INF_F
#define SENTINEL 0x7fffffff
#define FULLM 0xffffffffu

// Candidate pair layout: pair j -> g_pairs[2j]=(x0,x1,y0,y1), g_pairs[2j+1]=(z0,z1,w0,w1)
__device__ float4 g_pairs[NB * (NPTS / 2) * 2];
__device__ float4 g_pts[NB * NPTS];                // (x,y,z,|p|^2) by original index
// Partials, transposed for coalescing: [slice*3+k][query]
__device__ float  g_pScore[NENT * NQ];
__device__ int    g_pIdx[NENT * NQ];
// Tau pipeline: bucket mins [chunk*4+bucket][query], then tau per query
__device__ float  g_tc[NMINS * NQ];
__device__ float  g_tau[NQ];

__device__ __forceinline__ uint64_t dup2(float v) {
    uint64_t r; asm("mov.b64 %0,{%1,%1};" : "=l"(r) : "f"(v)); return r;
}
__device__ __forceinline__ uint64_t fma2(uint64_t a, uint64_t b, uint64_t c) {
    uint64_t d; asm("fma.rn.f32x2 %0,%1,%2,%3;" : "=l"(d) : "l"(a), "l"(b), "l"(c)); return d;
}
__device__ __forceinline__ void unpack2(uint64_t v, float& lo, float& hi) {
    asm("mov.b64 {%0,%1},%2;" : "=f"(lo), "=f"(hi) : "l"(v));
}

// Branchy insert (fast when guarded by a rare outer test) — used in k4.
#define INS3(bs0, bs1, bs2, bi0, bi1, bi2, s, id)            \
    if ((s) < (bs2)) {                                       \
        if ((s) < (bs1)) {                                   \
            bs2 = bs1; bi2 = bi1;                            \
            if ((s) < (bs0)) { bs1 = bs0; bi1 = bi0;         \
                               bs0 = (s); bi0 = (id); }      \
            else             { bs1 = (s); bi1 = (id); }      \
        } else { bs2 = (s); bi2 = (id); }                    \
    }

// Branchless (select-based) insert — used in k5 so loads can be pipelined.
#define FINS3(s0, s1, s2, i0, i1, i2, s, id) do {            \
    bool p2 = (s) < (s2);                                    \
    bool p1 = (s) < (s1);                                    \
    bool p0 = (s) < (s0);                                    \
    s2 = p1 ? (s1) : (p2 ? (s) : (s2));                      \
    i2 = p1 ? (i1) : (p2 ? (id) : (i2));                     \
    s1 = p0 ? (s0) : (p1 ? (s) : (s1));                      \
    i1 = p0 ? (i0) : (p1 ? (id) : (i1));                     \
    s0 = p0 ? (s) : (s0);                                    \
    i0 = p0 ? (id) : (i0);                                   \
} while (0)

// Fused prep + tau bucket-min kernel (R9/R12 config — sample = 2048).
#define K12_PREP_BLOCKS ((NB * REST) / 128)                    // = 96

__global__ void __launch_bounds__(128)
k12_prep_tau(const float* __restrict__ xyz1,
             const float* __restrict__ xyz2,
             const float* __restrict__ flow1) {
    const int tid = threadIdx.x;
    const int blk = blockIdx.x;

    if (blk >= 2048) {
        int e = (blk - 2048) * 128 + tid;          // 0 .. NB*REST-1
        int b = e / REST;
        int n = SAMPLE + (e - b * REST);           // SAMPLE .. NPTS-1
        const float* X = xyz1 + b * 3 * NPTS;
        const float* F = flow1 + b * 3 * NPTS;
        float px = X[n]            + F[n];
        float py = X[NPTS + n]     + F[NPTS + n];
        float pz = X[2 * NPTS + n] + F[2 * NPTS + n];
        float pw = fmaf(px, px, fmaf(py, py, pz * pz));
        g_pts[b * NPTS + n] = make_float4(px, py, pz, pw);
        float ox = __shfl_xor_sync(FULLM, px, 1);
        float oy = __shfl_xor_sync(FULLM, py, 1);
        float oz = __shfl_xor_sync(FULLM, pz, 1);
        float ow = __shfl_xor_sync(FULLM, pw, 1);
        if ((n & 1) == 0) {
            int j = b * (NPTS / 2) + (n >> 1);
            g_pairs[2 * j]     = make_float4(px, ox, py, oy);
            g_pairs[2 * j + 1] = make_float4(pz, oz, pw, ow);
        }
        return;
    }

    __shared__ float4 shp[CHPAIRS * 2];            // 2 KB chunk
    const int ch   = blk & (TCH - 1);
    const int qblk = blk >> 4;                     // 0..127; 64 qblks per batch
    const int b    = qblk >> 6;

    {
        const int c = ch * CHCAND + tid;
        const float* X = xyz1 + b * 3 * NPTS;
        const float* F = flow1 + b * 3 * NPTS;
        float px = X[c]            + F[c];
        float py = X[NPTS + c]     + F[NPTS + c];
        float pz = X[2 * NPTS + c] + F[2 * NPTS + c];
        float pw = fmaf(px, px, fmaf(py, py, pz * pz));
        float ox = __shfl_xor_sync(FULLM, px, 1);
        float oy = __shfl_xor_sync(FULLM, py, 1);
        float oz = __shfl_xor_sync(FULLM, pz, 1);
        float ow = __shfl_xor_sync(FULLM, pw, 1);
        if ((tid & 1) == 0) {
            int jj = tid >> 1;
            shp[2 * jj]     = make_float4(px, ox, py, oy);
            shp[2 * jj + 1] = make_float4(pz, oz, pw, ow);
        }
        if ((qblk & 63) == 0) {                    // writer block for (b, ch)
            g_pts[b * NPTS + c] = make_float4(px, py, pz, pw);
            if ((tid & 1) == 0) {
                int j = b * (NPTS / 2) + (c >> 1);
                g_pairs[2 * j]     = make_float4(px, ox, py, oy);
                g_pairs[2 * j + 1] = make_float4(pz, oz, pw, ow);
            }
        }
    }
    __syncthreads();

    const int q = qblk * 128 + tid;
    const int n = q & (NPTS - 1);
    const float* X2 = xyz2 + b * 3 * NPTS;
    const float qx = X2[n], qy = X2[NPTS + n], qz = X2[2 * NPTS + n];
    const uint64_t mx = dup2(-2.f * qx), my = dup2(-2.f * qy), mz = dup2(-2.f * qz);

    const ulonglong2* src = reinterpret_cast<const ulonglong2*>(shp);
    float m0 = INF, m1 = INF, m2 = INF, m3 = INF;
#pragma unroll 4
    for (int j = 0; j < CHPAIRS; j += 2) {
        ulonglong2 u0 = src[2 * j];
        ulonglong2 u1 = src[2 * j + 1];
        ulonglong2 v0 = src[2 * j + 2];
        ulonglong2 v1 = src[2 * j + 3];
        float a0, a1, c0, c1;
        unpack2(fma2(u0.x, mx, fma2(u0.y, my, fma2(u1.x, mz, u1.y))), a0, a1);
        unpack2(fma2(v0.x, mx, fma2(v0.y, my, fma2(v1.x, mz, v1.y))), c0, c1);
        m0 = fminf(m0, a0);
        m1 = fminf(m1, a1);
        m2 = fminf(m2, c0);
        m3 = fminf(m3, c1);
    }
    g_tc[(ch * 4 + 0) * NQ + q] = m0;
    g_tc[(ch * 4 + 1) * NQ + q] = m1;
    g_tc[(ch * 4 + 2) * NQ + q] = m2;
    g_tc[(ch * 4 + 3) * NQ + q] = m3;
}

// 3rd smallest of the 64 bucket mins (64 distinct candidates => >= global 3rd best).
__global__ void k3_tau2() {
    int q = blockIdx.x * blockDim.x + threadIdx.x;
    if (q >= NQ) return;
    float b0 = INF, b1 = INF, b2 = INF;
#pragma unroll 8
    for (int c = 0; c < NMINS; c++) {
        float s = g_tc[c * NQ + q];
        float t = fmaxf(b0, s);  b0 = fminf(b0, s);
        float u = fmaxf(b1, t);  b1 = fminf(b1, t);
        b2 = fminf(b2, u);
    }
    g_tau[q] = nextafterf(b2, CUDART_INF_F);
}

// 256 queries/block vs one 256-candidate slice (SLICES=32 -> grid 2048 for occupancy).
__global__ void __launch_bounds__(K4_THREADS)
k4_scan(const float* __restrict__ xyz2) {
    __shared__ float4 sh[SLICE_PAIRS * 2];   // 4 KB

    const int blk   = blockIdx.x;
    const int slice = blk & (SLICES - 1);
    const int qg    = blk >> 5;              // 0..63
    const int batch = qg >> 5;               // 32 qgroups per batch
    const int qbase = (qg & 31) * QPB;
    const int lane  = threadIdx.x & 31;
    const int w     = threadIdx.x >> 5;

    const float4* src = g_pairs + (size_t)(batch * (NPTS / 2) + slice * SLICE_PAIRS) * 2;
#pragma unroll
    for (int i = threadIdx.x; i < SLICE_PAIRS * 2; i += K4_THREADS)
        sh[i] = src[i];
    __syncthreads();

    const int qA = qbase + w * 64 + lane;
    const int qB = qA + 32;
    const int gqA = batch * NPTS + qA;
    const int gqB = batch * NPTS + qB;
    const float* X2 = xyz2 + batch * 3 * NPTS;
    const float aX = X2[qA], aY = X2[NPTS + qA], aZ = X2[2 * NPTS + qA];
    const float bX = X2[qB], bY = X2[NPTS + qB], bZ = X2[2 * NPTS + qB];

    const uint64_t Amx = dup2(-2.f * aX), Amy = dup2(-2.f * aY), Amz = dup2(-2.f * aZ);
    const uint64_t Bmx = dup2(-2.f * bX), Bmy = dup2(-2.f * bY), Bmz = dup2(-2.f * bZ);

    const float tA = g_tau[gqA];
    const float tB = g_tau[gqB];
    float As0 = tA, As1 = tA, As2 = tA;  int Ai0 = SENTINEL, Ai1 = SENTINEL, Ai2 = SENTINEL;
    float Bs0 = tB, Bs1 = tB, Bs2 = tB;  int Bi0 = SENTINEL, Bi1 = SENTINEL, Bi2 = SENTINEL;

    const uint32_t shbase = (uint32_t)__cvta_generic_to_shared(sh);
    const int cbase = slice * SLICE_CAND;

#pragma unroll 4
    for (int j = 0; j < SLICE_PAIRS; j += 2) {
        uint64_t xp0, yp0, zp0, wp0, xp1, yp1, zp1, wp1;
        const uint32_t addr = shbase + j * 32;
        asm("ld.shared.v2.u64 {%0,%1},[%2];"    : "=l"(xp0), "=l"(yp0) : "r"(addr));
        asm("ld.shared.v2.u64 {%0,%1},[%2+16];" : "=l"(zp0), "=l"(wp0) : "r"(addr));
        asm("ld.shared.v2.u64 {%0,%1},[%2+32];" : "=l"(xp1), "=l"(yp1) : "r"(addr));
        asm("ld.shared.v2.u64 {%0,%1},[%2+48];" : "=l"(zp1), "=l"(wp1) : "r"(addr));

        float a0, a1, a2, a3, b0, b1, b2, b3;
        unpack2(fma2(xp0, Amx, fma2(yp0, Amy, fma2(zp0, Amz, wp0))), a0, a1);
        unpack2(fma2(xp1, Amx, fma2(yp1, Amy, fma2(zp1, Amz, wp1))), a2, a3);
        unpack2(fma2(xp0, Bmx, fma2(yp0, Bmy, fma2(zp0, Bmz, wp0))), b0, b1);
        unpack2(fma2(xp1, Bmx, fma2(yp1, Bmy, fma2(zp1, Bmz, wp1))), b2, b3);

        if (fminf(fminf(a0, a1), fminf(a2, a3)) < As2) {
            const int id = cbase + 2 * j;
            INS3(As0, As1, As2, Ai0, Ai1, Ai2, a0, id);
            INS3(As0, As1, As2, Ai0, Ai1, Ai2, a1, id + 1);
            INS3(As0, As1, As2, Ai0, Ai1, Ai2, a2, id + 2);
            INS3(As0, As1, As2, Ai0, Ai1, Ai2, a3, id + 3);
        }
        if (fminf(fminf(b0, b1), fminf(b2, b3)) < Bs2) {
            const int id = cbase + 2 * j;
            INS3(Bs0, Bs1, Bs2, Bi0, Bi1, Bi2, b0, id);
            INS3(Bs0, Bs1, Bs2, Bi0, Bi1, Bi2, b1, id + 1);
            INS3(Bs0, Bs1, Bs2, Bi0, Bi1, Bi2, b2, id + 2);
            INS3(Bs0, Bs1, Bs2, Bi0, Bi1, Bi2, b3, id + 3);
        }
    }

    const int sb = slice * 3 * NQ;
    g_pScore[sb + 0 * NQ + gqA] = As0;  g_pIdx[sb + 0 * NQ + gqA] = Ai0;
    g_pScore[sb + 1 * NQ + gqA] = As1;  g_pIdx[sb + 1 * NQ + gqA] = Ai1;
    g_pScore[sb + 2 * NQ + gqA] = As2;  g_pIdx[sb + 2 * NQ + gqA] = Ai2;
    g_pScore[sb + 0 * NQ + gqB] = Bs0;  g_pIdx[sb + 0 * NQ + gqB] = Bi0;
    g_pScore[sb + 1 * NQ + gqB] = Bs1;  g_pIdx[sb + 1 * NQ + gqB] = Bi1;
    g_pScore[sb + 2 * NQ + gqB] = Bs2;  g_pIdx[sb + 2 * NQ + gqB] = Bi2;
}

// Four threads per query: each merges 24 entries branchless; 2 butterfly rounds
// (xor 1, xor 2) with lower-half-first ordering (strict < keeps low-index
// tie-break since slices are ascending index ranges). h==0 runs the epilogue.
__global__ void __launch_bounds__(256)
k5_final(const float* __restrict__ xyz2,
         const float* __restrict__ flow1,
         float* __restrict__ out) {
    const int i = blockIdx.x * 256 + threadIdx.x;   // 0 .. QT*NQ-1
    const int q = i >> 2;
    const int h = i & 3;
    const int b = q >> 13, n = q & (NPTS - 1);

    float bs0 = INF, bs1 = INF, bs2 = INF;
    int   bi0 = 0,   bi1 = 0,   bi2 = 0;
    const int ebase = h * HENT;
#pragma unroll
    for (int e = 0; e < HENT; e++) {
        float s  = g_pScore[(ebase + e) * NQ + q];
        int   iv = g_pIdx[(ebase + e) * NQ + q];
        FINS3(bs0, bs1, bs2, bi0, bi1, bi2, s, iv);
    }

    // Two butterfly rounds; in each pair the lower-h thread merges own-first.
#pragma unroll
    for (int off = 1; off <= 2; off <<= 1) {
        float rs0 = __shfl_xor_sync(FULLM, bs0, off);
        int   ri0 = __shfl_xor_sync(FULLM, bi0, off);
        float rs1 = __shfl_xor_sync(FULLM, bs1, off);
        int   ri1 = __shfl_xor_sync(FULLM, bi1, off);
        float rs2 = __shfl_xor_sync(FULLM, bs2, off);
        int   ri2 = __shfl_xor_sync(FULLM, bi2, off);

        bool low = (h & off) == 0;
        float m0 = low ? bs0 : rs0, m1 = low ? bs1 : rs1, m2 = low ? bs2 : rs2;
        int   j0 = low ? bi0 : ri0, j1 = low ? bi1 : ri1, j2 = low ? bi2 : ri2;
        float u0 = low ? rs0 : bs0, u1 = low ? rs1 : bs1, u2 = low ? rs2 : bs2;
        int   v0 = low ? ri0 : bi0, v1 = low ? ri1 : bi1, v2 = low ? ri2 : bi2;
        FINS3(m0, m1, m2, j0, j1, j2, u0, v0);
        FINS3(m0, m1, m2, j0, j1, j2, u1, v1);
        FINS3(m0, m1, m2, j0, j1, j2, u2, v2);
        bs0 = m0; bs1 = m1; bs2 = m2;
        bi0 = j0; bi1 = j1; bi2 = j2;
    }

    if (h == 0) {
        const float* X2 = xyz2 + b * 3 * NPTS;
        const float qx = X2[n], qy = X2[NPTS + n], qz = X2[2 * NPTS + n];

        const float4* pts = g_pts + b * NPTS;
        int   pp[3] = { bi0, bi1, bi2 };
        float wk[3];
        float wsum = 0.f;
#pragma unroll
        for (int k = 0; k < 3; k++) {
            float4 p = pts[pp[k]];
            float dx = p.x - qx, dy = p.y - qy, dz = p.z - qz;
            float d = sqrtf(fmaf(dx, dx, fmaf(dy, dy, dz * dz)));
            d = fmaxf(d, 1e-10f);
            float inv = 1.0f / d;
            wk[k] = inv;
            wsum += inv;
        }
        const float rs = 1.0f / wsum;

        const float* F = flow1 + b * 3 * NPTS;
        float fx = 0.f, fy = 0.f, fz = 0.f;
#pragma unroll
        for (int k = 0; k < 3; k++) {
            int o = pp[k];
            float ww = wk[k] * rs;
            fx = fmaf(ww, F[o],            fx);
            fy = fmaf(ww, F[NPTS + o],     fy);
            fz = fmaf(ww, F[2 * NPTS + o], fz);
        }

        float* O = out + b * 3 * NPTS;
        O[n]            = qx - fx;
        O[NPTS + n]     = qy - fy;
        O[2 * NPTS + n] = qz - fz;
    }
}

extern "C" void kernel_launch(void* const* d_in, const int* in_sizes, int n_in,
                              void* d_out, int out_size) {
    const float* xyz1  = (const float*)d_in[0];
    const float* xyz2  = (const float*)d_in[1];
    const float* flow1 = (const float*)d_in[2];
    float* out = (float*)d_out;

    k12_prep_tau<<<2048 + K12_PREP_BLOCKS, 128>>>(xyz1, xyz2, flow1);  // 2144 blocks
    k3_tau2<<<(NQ + 255) / 256, 256>>>();
    k4_scan<<<(NQ / QPB) * SLICES, K4_THREADS>>>(xyz2);                // 2048 blocks
    k5_final<<<(QT * NQ) / 256, 256>>>(xyz2, flow1, out);              // 256 blocks
}